// round 1
// baseline (speedup 1.0000x reference)
#include <cuda_runtime.h>

// DIN attention-seq-pooling, folded form.
// B=4096 blocks, 256 threads, thread t = token t.
//
// preact1[t] = qW_b + k_t @ W1eff_b        (64x80 per token)
// h1 = sigmoid(preact1); preact2 = h1 @ W2 + b2 (80x40)
// score = sigmoid(preact2) @ Wd + bd ; masked t>=L -> 0
// out[b] = sum_t score_t * k_t

#define TT 200
#define EE 64
#define HH1 80
#define HH2 40
#define KSTRIDE 65   // 65 mod 32 == 1 -> conflict-free column reads

typedef unsigned long long ull;

__device__ __forceinline__ ull pack2(float lo, float hi) {
    ull r;
    asm("mov.b64 %0, {%1, %2};" : "=l"(r) : "f"(lo), "f"(hi));
    return r;
}
__device__ __forceinline__ void unpack2(ull v, float& lo, float& hi) {
    asm("mov.b64 {%0, %1}, %2;" : "=f"(lo), "=f"(hi) : "l"(v));
}
__device__ __forceinline__ ull fma2(ull a, ull b, ull c) {
    ull d;
    asm("fma.rn.f32x2 %0, %1, %2, %3;" : "=l"(d) : "l"(a), "l"(b), "l"(c));
    return d;
}
__device__ __forceinline__ float sigmoidf_fast(float x) {
    float e = __expf(-x);
    return __fdividef(1.0f, 1.0f + e);
}

// dynamic shared layout (floats):
//  [0, 13000)            sK       200 x 65
//  [13000, 18120)        sW1eff   64 x 80
//  [18120, 21320)        sW2      80 x 40
//  [21320, 21400)        sQW      80
//  [21400, 21464)        sQ       64
//  [21464, 21504)        sB2      40
//  [21504, 21544)        sWd      40
//  [21544, 21744)        sScore   200
#define SM_K      0
#define SM_W1EFF  13000
#define SM_W2     18120
#define SM_QW     21320
#define SM_Q      21400
#define SM_B2     21464
#define SM_WD     21504
#define SM_SCORE  21544
#define SM_FLOATS 21744

__global__ void __launch_bounds__(256, 2)
din_pool_kernel(const float* __restrict__ query,
                const float* __restrict__ keys,
                const void*  __restrict__ klen,
                const float* __restrict__ W1,
                const float* __restrict__ b1,
                const float* __restrict__ W2,
                const float* __restrict__ b2,
                const float* __restrict__ Wd,
                const float* __restrict__ bd,
                float* __restrict__ out)
{
    extern __shared__ float smem[];
    const int b   = blockIdx.x;
    const int tid = threadIdx.x;

    // ---- keys_length dtype detection (int64 vs silently-int32 jax) ----
    const long long* L64 = (const long long*)klen;
    const int*       L32 = (const int*)klen;
    bool is64 = ((ull)L64[0] <= 0xFFFFFFFFull) && ((ull)L64[1] <= 0xFFFFFFFFull) &&
                ((ull)L64[2] <= 0xFFFFFFFFull) && ((ull)L64[3] <= 0xFFFFFFFFull);
    int L = is64 ? (int)L64[b] : L32[b];
    if (L < 0) L = 0;
    if (L > TT) L = TT;

    // ---- stage q ----
    if (tid < EE) smem[SM_Q + tid] = query[(size_t)b * EE + tid];
    __syncthreads();

    // ---- qW[h] = b1[h] + sum_e q_e * (W1a + W1c) ----
    for (int h = tid; h < HH1; h += 256) {
        float s = b1[h];
        #pragma unroll 8
        for (int e = 0; e < EE; e++)
            s += smem[SM_Q + e] * (W1[e * HH1 + h] + W1[(128 + e) * HH1 + h]);
        smem[SM_QW + h] = s;
    }
    // ---- W1eff[e][h] = W1b - W1c + q_e * W1d ----
    for (int i = tid; i < EE * HH1; i += 256) {
        int e = i / HH1, h = i - e * HH1;
        smem[SM_W1EFF + i] = W1[(64 + e) * HH1 + h] - W1[(128 + e) * HH1 + h]
                           + smem[SM_Q + e] * W1[(192 + e) * HH1 + h];
    }
    // ---- copy W2, b2, Wd ----
    for (int i = tid; i < HH1 * HH2; i += 256) smem[SM_W2 + i] = W2[i];
    if (tid < HH2) { smem[SM_B2 + tid] = b2[tid]; smem[SM_WD + tid] = Wd[tid]; }

    // ---- stage keys[b, 0:L, :] -> sK, padded stride 65 ----
    {
        const float* kb = keys + (size_t)b * TT * EE;
        int nk = L * EE;
        for (int i = tid; i < nk; i += 256) {
            int t = i >> 6, e = i & 63;
            smem[SM_K + t * KSTRIDE + e] = kb[i];
        }
    }
    __syncthreads();

    // ---- per-token MLP ----
    const int t = tid;
    float score = 0.0f;
    if (t < L) {
        ull acc[HH1 / 2];
        const ull* qwp = (const ull*)&smem[SM_QW];
        #pragma unroll
        for (int hp = 0; hp < HH1 / 2; hp++) acc[hp] = qwp[hp];

        const float* krow = &smem[SM_K + t * KSTRIDE];
        for (int e = 0; e < EE; e++) {
            float kv = krow[e];
            ull kv2 = pack2(kv, kv);
            const ull* wrow = (const ull*)&smem[SM_W1EFF + e * HH1];
            #pragma unroll
            for (int hp = 0; hp < HH1 / 2; hp++)
                acc[hp] = fma2(kv2, wrow[hp], acc[hp]);
        }

        // sigmoid layer 1, in place
        #pragma unroll
        for (int hp = 0; hp < HH1 / 2; hp++) {
            float a, c; unpack2(acc[hp], a, c);
            acc[hp] = pack2(sigmoidf_fast(a), sigmoidf_fast(c));
        }

        // layer 2: preact2[j] = b2[j] + sum_h h1[h]*W2[h][j]
        ull p2[HH2 / 2];
        const ull* b2p = (const ull*)&smem[SM_B2];
        #pragma unroll
        for (int jp = 0; jp < HH2 / 2; jp++) p2[jp] = b2p[jp];

        #pragma unroll
        for (int hp = 0; hp < HH1 / 2; hp++) {
            float h0, h1v; unpack2(acc[hp], h0, h1v);
            {
                ull hv2 = pack2(h0, h0);
                const ull* w2row = (const ull*)&smem[SM_W2 + (2 * hp) * HH2];
                #pragma unroll
                for (int jp = 0; jp < HH2 / 2; jp++)
                    p2[jp] = fma2(hv2, w2row[jp], p2[jp]);
            }
            {
                ull hv2 = pack2(h1v, h1v);
                const ull* w2row = (const ull*)&smem[SM_W2 + (2 * hp + 1) * HH2];
                #pragma unroll
                for (int jp = 0; jp < HH2 / 2; jp++)
                    p2[jp] = fma2(hv2, w2row[jp], p2[jp]);
            }
        }

        // head: score = bd + sum_j sigmoid(preact2[j]) * Wd[j]
        float s = bd[0];
        #pragma unroll
        for (int jp = 0; jp < HH2 / 2; jp++) {
            float a, c; unpack2(p2[jp], a, c);
            s += sigmoidf_fast(a) * smem[SM_WD + 2 * jp]
               + sigmoidf_fast(c) * smem[SM_WD + 2 * jp + 1];
        }
        score = s;
    }
    if (t < TT) smem[SM_SCORE + t] = score;
    __syncthreads();

    // ---- epilogue: out[b][e] = sum_{t<L} score_t * k[t][e] ----
    if (tid < EE) {
        float s = 0.0f;
        for (int tt = 0; tt < L; tt++)
            s += smem[SM_SCORE + tt] * smem[SM_K + tt * KSTRIDE + tid];
        out[(size_t)b * EE + tid] = s;
    }
}

extern "C" void kernel_launch(void* const* d_in, const int* in_sizes, int n_in,
                              void* d_out, int out_size)
{
    const float* query = (const float*)d_in[0];
    const float* keys  = (const float*)d_in[1];
    const void*  klen  = d_in[2];
    const float* W1    = (const float*)d_in[3];
    const float* b1    = (const float*)d_in[4];
    const float* W2    = (const float*)d_in[5];
    const float* b2    = (const float*)d_in[6];
    const float* Wd    = (const float*)d_in[7];
    const float* bd    = (const float*)d_in[8];
    float* out = (float*)d_out;

    const int B = in_sizes[0] / EE;  // 4096
    const int smem_bytes = SM_FLOATS * sizeof(float);  // ~87 KB

    cudaFuncSetAttribute(din_pool_kernel,
                         cudaFuncAttributeMaxDynamicSharedMemorySize, smem_bytes);

    din_pool_kernel<<<B, 256, smem_bytes>>>(query, keys, klen, W1, b1, W2, b2,
                                            Wd, bd, out);
}

// round 2
// speedup vs baseline: 1.4482x; 1.4482x over previous
#include <cuda_runtime.h>

// DIN attention-seq-pooling, round 2: register-tiled MLP.
// Layout: block = 128 thr = 4 warps, one batch b per block.
// Warp w handles token chunks c in {w, w+4} (32 tokens each), two passes of
// 16 tokens. Within a warp: lane = tg (lane&7, token subgroup) x hg (lane>>3,
// h quarter). Each thread: 2 tokens x 20 h accumulators (20 ull f32x2).
// Weights live in smem (conflict-free LDS.128), keys stream from global.

#define TT 200
#define EE 64
#define HH1 80
#define HH2 40

typedef unsigned long long ull;

__device__ float g_W1sum[EE * HH1];   // W1a + W1c
__device__ float g_W1bc[EE * HH1];    // W1b - W1c
__device__ float g_qW[4096 * HH1];    // b1 + q @ W1sum, per batch

__device__ __forceinline__ ull pack2(float lo, float hi) {
    ull r; asm("mov.b64 %0, {%1, %2};" : "=l"(r) : "f"(lo), "f"(hi)); return r;
}
__device__ __forceinline__ void unpack2(ull v, float& lo, float& hi) {
    asm("mov.b64 {%0, %1}, %2;" : "=f"(lo), "=f"(hi) : "l"(v));
}
__device__ __forceinline__ ull fma2(ull a, ull b, ull c) {
    ull d; asm("fma.rn.f32x2 %0, %1, %2, %3;" : "=l"(d) : "l"(a), "l"(b), "l"(c)); return d;
}
__device__ __forceinline__ float sigmoidf_fast(float x) {
    float e = __expf(-x);
    return __fdividef(1.0f, 1.0f + e);
}

// ---------------- prep kernels ----------------
__global__ void prep_w1(const float* __restrict__ W1) {
    int i = blockIdx.x * 256 + threadIdx.x;
    if (i < EE * HH1) {
        float a = W1[i];
        float bv = W1[EE * HH1 + i];
        float c = W1[2 * EE * HH1 + i];
        g_W1sum[i] = a + c;
        g_W1bc[i]  = bv - c;
    }
}

__global__ void prep_qw(const float* __restrict__ query, const float* __restrict__ b1) {
    __shared__ float sq[EE];
    int b = blockIdx.x, tid = threadIdx.x;
    if (tid < EE) sq[tid] = query[b * EE + tid];
    __syncthreads();
    if (tid < HH1) {
        float acc = b1[tid];
        #pragma unroll 8
        for (int e = 0; e < EE; e++)
            acc += sq[e] * g_W1sum[e * HH1 + tid];
        g_qW[b * HH1 + tid] = acc;
    }
}

// ---------------- main kernel ----------------
// smem layout (floats):
#define SM_W1EFF 0                 // 64 x 80 = 5120, row stride 80
#define SM_W2    5120              // groups-of-20 rows, stride 44, group skew 884 -> 3532
#define SM_QW    8652              // 80
#define SM_B2    8732              // 40
#define SM_WD    8772              // 40
#define SM_SCORE 8812              // 200
#define SM_PART  9012              // 128 (also stages q during prologue)
#define SM_TOT   9140

__device__ __forceinline__ float4 ld_guard(const float* p, bool v) {
    float4 z = make_float4(0.f, 0.f, 0.f, 0.f);
    return v ? *(const float4*)p : z;
}

__device__ __forceinline__ void l1_step(float k0, float k1, const float* wrow,
                                        ull (&a0)[10], ull (&a1)[10]) {
    ull k02 = pack2(k0, k0), k12 = pack2(k1, k1);
    ulonglong2 w0 = *(const ulonglong2*)(wrow);
    ulonglong2 w1 = *(const ulonglong2*)(wrow + 4);
    ulonglong2 w2 = *(const ulonglong2*)(wrow + 8);
    ulonglong2 w3 = *(const ulonglong2*)(wrow + 12);
    ulonglong2 w4 = *(const ulonglong2*)(wrow + 16);
    a0[0] = fma2(k02, w0.x, a0[0]); a1[0] = fma2(k12, w0.x, a1[0]);
    a0[1] = fma2(k02, w0.y, a0[1]); a1[1] = fma2(k12, w0.y, a1[1]);
    a0[2] = fma2(k02, w1.x, a0[2]); a1[2] = fma2(k12, w1.x, a1[2]);
    a0[3] = fma2(k02, w1.y, a0[3]); a1[3] = fma2(k12, w1.y, a1[3]);
    a0[4] = fma2(k02, w2.x, a0[4]); a1[4] = fma2(k12, w2.x, a1[4]);
    a0[5] = fma2(k02, w2.y, a0[5]); a1[5] = fma2(k12, w2.y, a1[5]);
    a0[6] = fma2(k02, w3.x, a0[6]); a1[6] = fma2(k12, w3.x, a1[6]);
    a0[7] = fma2(k02, w3.y, a0[7]); a1[7] = fma2(k12, w3.y, a1[7]);
    a0[8] = fma2(k02, w4.x, a0[8]); a1[8] = fma2(k12, w4.x, a1[8]);
    a0[9] = fma2(k02, w4.y, a0[9]); a1[9] = fma2(k12, w4.y, a1[9]);
}

__global__ void __launch_bounds__(128, 4)
din_pool_kernel(const float* __restrict__ query,
                const float* __restrict__ keys,
                const void*  __restrict__ klen,
                const float* __restrict__ W1,
                const float* __restrict__ W2,
                const float* __restrict__ Wd,
                const float* __restrict__ b2,
                const float* __restrict__ bd,
                float* __restrict__ out)
{
    __shared__ float smem[SM_TOT];
    const int b   = blockIdx.x;
    const int tid = threadIdx.x;
    const int wid = tid >> 5;
    const int lane = tid & 31;
    const int tg = lane & 7;
    const int hg = lane >> 3;

    // ---- length (int64 vs silently-int32 jax) ----
    const long long* L64 = (const long long*)klen;
    const int*       L32 = (const int*)klen;
    bool is64 = ((ull)L64[0] <= 0xFFFFFFFFull) && ((ull)L64[1] <= 0xFFFFFFFFull) &&
                ((ull)L64[2] <= 0xFFFFFFFFull) && ((ull)L64[3] <= 0xFFFFFFFFull);
    int L = is64 ? (int)L64[b] : L32[b];
    if (L < 0) L = 0;
    if (L > TT) L = TT;

    // ---- prologue ----
    if (tid < EE) smem[SM_PART + tid] = query[b * EE + tid];  // stage q
    if (tid < HH1) smem[SM_QW + tid] = g_qW[b * HH1 + tid];
    if (tid < HH2) { smem[SM_B2 + tid] = b2[tid]; smem[SM_WD + tid] = Wd[tid]; }
    for (int i = tid; i < TT; i += 128) smem[SM_SCORE + i] = 0.0f;
    // W2 copy with group skew: addr(h,j) = (h/20)*884 + (h%20)*44 + j
    for (int i = tid; i < HH1 * HH2; i += 128) {
        int h = i / HH2, j = i - h * HH2;
        int g = h / 20, hh = h - g * 20;
        smem[SM_W2 + g * 884 + hh * 44 + j] = W2[i];
    }
    __syncthreads();
    // W1eff[e][h] = W1bc + q_e * W1d
    const float* W1d = W1 + 3 * EE * HH1;
    for (int e = wid; e < EE; e += 4) {
        float qv = smem[SM_PART + e];
        #pragma unroll
        for (int h = lane; h < HH1; h += 32)
            smem[SM_W1EFF + e * HH1 + h] = g_W1bc[e * HH1 + h] + qv * W1d[e * HH1 + h];
    }
    __syncthreads();

    const float bdv = bd[0];
    const float* kbase = keys + (size_t)b * TT * EE;
    const ull* qwp = (const ull*)&smem[SM_QW + 20 * hg];

    // ---- token chunks ----
    for (int c = wid; c < 7; c += 4) {
        if (32 * c >= L) continue;
        for (int p = 0; p < 2; p++) {
            int tbase = 32 * c + 16 * p;
            if (tbase >= L) break;
            int tok0 = tbase + tg;
            int tok1 = tok0 + 8;
            bool v0 = tok0 < TT, v1 = tok1 < TT;
            const float* kp0 = kbase + tok0 * EE;
            const float* kp1 = kbase + tok1 * EE;

            ull a0[10], a1[10];
            #pragma unroll
            for (int u = 0; u < 10; u++) { a0[u] = qwp[u]; a1[u] = qwp[u]; }

            // layer 1: preact += k @ W1eff, e in chunks of 4, double-buffered
            float4 c0 = ld_guard(kp0, v0), c1 = ld_guard(kp1, v1);
            #pragma unroll 2
            for (int ec = 0; ec < EE; ec += 4) {
                float4 n0, n1;
                if (ec < EE - 4) {
                    n0 = ld_guard(kp0 + ec + 4, v0);
                    n1 = ld_guard(kp1 + ec + 4, v1);
                }
                const float* wr = &smem[SM_W1EFF + ec * HH1 + 20 * hg];
                l1_step(c0.x, c1.x, wr,            a0, a1);
                l1_step(c0.y, c1.y, wr + HH1,      a0, a1);
                l1_step(c0.z, c1.z, wr + 2 * HH1,  a0, a1);
                l1_step(c0.w, c1.w, wr + 3 * HH1,  a0, a1);
                if (ec < EE - 4) { c0 = n0; c1 = n1; }
            }

            // sigmoid layer 1
            #pragma unroll
            for (int u = 0; u < 10; u++) {
                float x, y;
                unpack2(a0[u], x, y);
                a0[u] = pack2(sigmoidf_fast(x), sigmoidf_fast(y));
                unpack2(a1[u], x, y);
                a1[u] = pack2(sigmoidf_fast(x), sigmoidf_fast(y));
            }

            // layer 2 in j-chunks of 8, partial over my 20 h, butterfly over hg
            float sc0 = 0.0f, sc1 = 0.0f;
            const float* w2g = &smem[SM_W2 + hg * 884];
            for (int jc = 0; jc < 5; jc++) {
                ull p20[4] = {0, 0, 0, 0}, p21[4] = {0, 0, 0, 0};
                #pragma unroll
                for (int u = 0; u < 10; u++) {
                    float hA, hB, hC, hD;
                    unpack2(a0[u], hA, hB);
                    unpack2(a1[u], hC, hD);
                    const float* w2a = w2g + (2 * u) * 44 + jc * 8;
                    ulonglong2 wa0 = *(const ulonglong2*)(w2a);
                    ulonglong2 wa1 = *(const ulonglong2*)(w2a + 4);
                    ulonglong2 wb0 = *(const ulonglong2*)(w2a + 44);
                    ulonglong2 wb1 = *(const ulonglong2*)(w2a + 48);
                    ull h2;
                    h2 = pack2(hA, hA);
                    p20[0] = fma2(h2, wa0.x, p20[0]); p20[1] = fma2(h2, wa0.y, p20[1]);
                    p20[2] = fma2(h2, wa1.x, p20[2]); p20[3] = fma2(h2, wa1.y, p20[3]);
                    h2 = pack2(hB, hB);
                    p20[0] = fma2(h2, wb0.x, p20[0]); p20[1] = fma2(h2, wb0.y, p20[1]);
                    p20[2] = fma2(h2, wb1.x, p20[2]); p20[3] = fma2(h2, wb1.y, p20[3]);
                    h2 = pack2(hC, hC);
                    p21[0] = fma2(h2, wa0.x, p21[0]); p21[1] = fma2(h2, wa0.y, p21[1]);
                    p21[2] = fma2(h2, wa1.x, p21[2]); p21[3] = fma2(h2, wa1.y, p21[3]);
                    h2 = pack2(hD, hD);
                    p21[0] = fma2(h2, wb0.x, p21[0]); p21[1] = fma2(h2, wb0.y, p21[1]);
                    p21[2] = fma2(h2, wb1.x, p21[2]); p21[3] = fma2(h2, wb1.y, p21[3]);
                }
                // butterfly sum over hg (lanes xor 8, 16)
                #pragma unroll
                for (int u = 0; u < 4; u++) {
                    float lo, hi;
                    unpack2(p20[u], lo, hi);
                    lo += __shfl_xor_sync(0xffffffffu, lo, 8);
                    hi += __shfl_xor_sync(0xffffffffu, hi, 8);
                    lo += __shfl_xor_sync(0xffffffffu, lo, 16);
                    hi += __shfl_xor_sync(0xffffffffu, hi, 16);
                    p20[u] = pack2(lo, hi);
                    unpack2(p21[u], lo, hi);
                    lo += __shfl_xor_sync(0xffffffffu, lo, 8);
                    hi += __shfl_xor_sync(0xffffffffu, hi, 8);
                    lo += __shfl_xor_sync(0xffffffffu, lo, 16);
                    hi += __shfl_xor_sync(0xffffffffu, hi, 16);
                    p21[u] = pack2(lo, hi);
                }
                // my hg's 2-j slice: sigmoid + head dot
                ull m0 = (hg & 1) ? p20[1] : p20[0];
                ull m1 = (hg & 1) ? p20[3] : p20[2];
                ull mine0 = (hg & 2) ? m1 : m0;
                m0 = (hg & 1) ? p21[1] : p21[0];
                m1 = (hg & 1) ? p21[3] : p21[2];
                ull mine1 = (hg & 2) ? m1 : m0;
                int j0 = jc * 8 + 2 * hg;
                float blo = smem[SM_B2 + j0], bhi = smem[SM_B2 + j0 + 1];
                float wlo = smem[SM_WD + j0], whi = smem[SM_WD + j0 + 1];
                float lo, hi;
                unpack2(mine0, lo, hi);
                sc0 += sigmoidf_fast(lo + blo) * wlo + sigmoidf_fast(hi + bhi) * whi;
                unpack2(mine1, lo, hi);
                sc1 += sigmoidf_fast(lo + blo) * wlo + sigmoidf_fast(hi + bhi) * whi;
            }
            // sum score slices over hg
            sc0 += __shfl_xor_sync(0xffffffffu, sc0, 8);
            sc0 += __shfl_xor_sync(0xffffffffu, sc0, 16);
            sc1 += __shfl_xor_sync(0xffffffffu, sc1, 8);
            sc1 += __shfl_xor_sync(0xffffffffu, sc1, 16);
            if (hg == 0) {
                if (tok0 < L) smem[SM_SCORE + tok0] = sc0 + bdv;
                if (tok1 < L) smem[SM_SCORE + tok1] = sc1 + bdv;
            }
        }
    }
    __syncthreads();

    // ---- epilogue: out[e] = sum_t score_t * k[t][e], split even/odd t ----
    {
        int g = tid >> 6, e = tid & 63;
        float acc = 0.0f;
        const float* kp = kbase + e;
        #pragma unroll 4
        for (int t = g; t < L; t += 2)
            acc += smem[SM_SCORE + t] * kp[t * EE];
        smem[SM_PART + tid] = acc;
    }
    __syncthreads();
    if (tid < EE)
        out[b * EE + tid] = smem[SM_PART + tid] + smem[SM_PART + EE + tid];
}

extern "C" void kernel_launch(void* const* d_in, const int* in_sizes, int n_in,
                              void* d_out, int out_size)
{
    const float* query = (const float*)d_in[0];
    const float* keys  = (const float*)d_in[1];
    const void*  klen  = d_in[2];
    const float* W1    = (const float*)d_in[3];
    const float* b1    = (const float*)d_in[4];
    const float* W2    = (const float*)d_in[5];
    const float* b2    = (const float*)d_in[6];
    const float* Wd    = (const float*)d_in[7];
    const float* bd    = (const float*)d_in[8];
    float* out = (float*)d_out;

    const int B = in_sizes[0] / EE;  // 4096

    prep_w1<<<(EE * HH1 + 255) / 256, 256>>>(W1);
    prep_qw<<<B, 128>>>(query, b1);
    din_pool_kernel<<<B, 128>>>(query, keys, klen, W1, W2, Wd, b2, bd, out);
}

// round 5
// speedup vs baseline: 2.3924x; 1.6520x over previous
#include <cuda_runtime.h>
#include <cstdint>

// DIN attention-seq-pooling, round 5: warp-level mma.sync tf32 (base-target).
// Fix vs round 4: h1 buffer stride 84 (was 68 < 80 cols -> row aliasing +
// region overflow into qW). CTA = one batch, 4 warps; warp owns 16-token
// M-tiles round-robin.
//  MMA1: D1[16,80] = k[16,64] @ B1eff[64,80]  (B1eff per-batch, tf32)
//  h1 = sigmoid(D1 + qW) -> per-warp smem buffer (tf32 bits)
//  MMA2: D2[16,40] = h1[16,80] @ W2T[80,40]
//  score = sigmoid(D2+b2)@Wd + bd, mask t<L; pool out = sum score_t * k_t.

#define TT 200
#define EE 64
#define HH1 80
#define HH2 40
#define KSTRIDE 68     // k / B1eff stride: ≡4 mod 32 -> conflict-free frags
#define H1STRIDE 84    // h1 stride: >=80, ≡20 mod 32 -> conflict-free frags
#define W2TSTRIDE 84

typedef unsigned long long ull;

__device__ float  g_W1sum[EE * HH1];      // W1a + W1c
__device__ float2 g_W1pair[EE * HH1];     // {W1b - W1c, W1d}, layout [e][n]
__device__ float  g_qW[4096 * HH1];       // b1 + q @ W1sum
__device__ unsigned g_W2T[HH2 * W2TSTRIDE]; // tf32 image, [n][k] k<80 else 0

__device__ __forceinline__ unsigned cvt_tf32(float x) {
    unsigned r; asm("cvt.rna.tf32.f32 %0, %1;" : "=r"(r) : "f"(x)); return r;
}
__device__ __forceinline__ float sigmoidf_fast(float x) {
    return __fdividef(1.0f, 1.0f + __expf(-x));
}
__device__ __forceinline__ void mma_tf32(float* d, unsigned a0, unsigned a1,
                                         unsigned a2, unsigned a3,
                                         unsigned b0, unsigned b1) {
    asm volatile(
        "mma.sync.aligned.m16n8k8.row.col.f32.tf32.tf32.f32 "
        "{%0,%1,%2,%3}, {%4,%5,%6,%7}, {%8,%9}, {%0,%1,%2,%3};"
        : "+f"(d[0]), "+f"(d[1]), "+f"(d[2]), "+f"(d[3])
        : "r"(a0), "r"(a1), "r"(a2), "r"(a3), "r"(b0), "r"(b1));
}

// ---------------- prep kernels ----------------
__global__ void prep_pack(const float* __restrict__ W1, const float* __restrict__ W2) {
    int i = blockIdx.x * 256 + threadIdx.x;
    if (i < EE * HH1) {                    // i = e*80+n
        g_W1sum[i] = W1[i] + W1[2 * EE * HH1 + i];
        float2 p;
        p.x = W1[EE * HH1 + i] - W1[2 * EE * HH1 + i];
        p.y = W1[3 * EE * HH1 + i];
        g_W1pair[i] = p;
    }
    if (i < HH2 * W2TSTRIDE) {
        int n = i / W2TSTRIDE, k = i - n * W2TSTRIDE;
        float v = (k < HH1) ? W2[k * HH2 + n] : 0.0f;
        g_W2T[i] = cvt_tf32(v);
    }
}

__global__ void prep_qw(const float* __restrict__ query, const float* __restrict__ b1) {
    __shared__ float sq[EE];
    int b = blockIdx.x, tid = threadIdx.x;
    if (tid < EE) sq[tid] = query[b * EE + tid];
    __syncthreads();
    if (tid < HH1) {
        float acc = b1[tid];
        #pragma unroll 8
        for (int e = 0; e < EE; e++)
            acc += sq[e] * g_W1sum[e * HH1 + tid];
        g_qW[b * HH1 + tid] = acc;
    }
}

// ---------------- smem layout (float index) ----------------
#define SM_K    0                         // 208 x 68 = 14144
#define SM_B1   14144                     // 80 x 68 = 5440 (tf32 bits, [n][e])
#define SM_W2T  19584                     // 40 x 84 = 3360 (tf32 bits)
#define SM_H1   22944                     // 4 warps x 16 x 84 = 5376 (tf32 bits)
#define SM_QW   28320                     // 80
#define SM_Q    28400                     // 64
#define SM_B2V  28464                     // 40
#define SM_WD   28504                     // 40
#define SM_SSC  28544                     // 208
#define SM_PART 28752                     // 128
#define SM_FLOATS 28880
#define SM_BYTES (SM_FLOATS * 4)          // 115520

__global__ void __launch_bounds__(128, 2)
din_mma_kernel(const float* __restrict__ query,
               const float* __restrict__ keys,
               const void*  __restrict__ klen,
               const float* __restrict__ b2,
               const float* __restrict__ Wd,
               const float* __restrict__ bd,
               float* __restrict__ out)
{
    extern __shared__ float smf[];
    unsigned* smu = (unsigned*)smf;
    const int b    = blockIdx.x;
    const int tid  = threadIdx.x;
    const int wid  = tid >> 5;
    const int lane = tid & 31;
    const int gr   = lane >> 2;     // group row 0..7
    const int tg   = lane & 3;      // thread-in-group 0..3

    // ---- length (int64 vs silently-int32 jax) ----
    const long long* L64 = (const long long*)klen;
    const int*       L32 = (const int*)klen;
    bool is64 = ((ull)L64[0] <= 0xFFFFFFFFull) && ((ull)L64[1] <= 0xFFFFFFFFull) &&
                ((ull)L64[2] <= 0xFFFFFFFFull) && ((ull)L64[3] <= 0xFFFFFFFFull);
    int L = is64 ? (int)L64[b] : L32[b];
    if (L < 0) L = 0;
    if (L > TT) L = TT;
    if (L == 0) {
        if (tid < EE) out[b * EE + tid] = 0.0f;
        return;
    }
    const int ntiles = (L + 15) >> 4;

    // ---- stage scalars / W2T / k tile ----
    if (tid < EE)  smf[SM_Q + tid]  = query[b * EE + tid];
    if (tid < HH1) smf[SM_QW + tid] = g_qW[b * HH1 + tid];
    if (tid < HH2) { smf[SM_B2V + tid] = b2[tid]; smf[SM_WD + tid] = Wd[tid]; }
    {
        const uint4* src = (const uint4*)g_W2T;
        uint4* dst = (uint4*)&smu[SM_W2T];
        for (int i = tid; i < HH2 * W2TSTRIDE / 4; i += 128) dst[i] = src[i];
    }
    {
        const float* kb = keys + (size_t)b * TT * EE;
        const int nrows = ntiles * 16;
        for (int i = tid; i < nrows * 16; i += 128) {
            int r = i >> 4, c4 = (i & 15) * 4;
            float4 v = make_float4(0.f, 0.f, 0.f, 0.f);
            if (r < TT) v = *(const float4*)(kb + (size_t)r * EE + c4);
            *(float4*)&smf[SM_K + r * KSTRIDE + c4] = v;
        }
    }
    __syncthreads();

    // ---- B1eff: [n][e], tf32 bits:  bc + q_e * d ----
    for (int i = tid; i < EE * HH1; i += 128) {
        int n = i % HH1, e = i / HH1;
        float2 p = g_W1pair[e * HH1 + n];
        smu[SM_B1 + n * KSTRIDE + e] = cvt_tf32(p.x + smf[SM_Q + e] * p.y);
    }
    __syncthreads();

    const float bdv = bd[0];
    unsigned* h1 = &smu[SM_H1 + wid * 16 * H1STRIDE];

    // ---- warp-owned 16-token tiles ----
    for (int mt = wid; mt < ntiles; mt += 4) {
        const int rbase = mt * 16;

        // MMA1: D1[16,80] = k @ B1eff
        float d1[10][4];
        #pragma unroll
        for (int nf = 0; nf < 10; nf++)
            d1[nf][0] = d1[nf][1] = d1[nf][2] = d1[nf][3] = 0.0f;

        #pragma unroll
        for (int ks = 0; ks < 8; ks++) {
            const float* ka = &smf[SM_K + ks * 8 + tg];
            unsigned a0 = cvt_tf32(ka[(rbase + gr) * KSTRIDE]);
            unsigned a1 = cvt_tf32(ka[(rbase + gr + 8) * KSTRIDE]);
            unsigned a2 = cvt_tf32(ka[(rbase + gr) * KSTRIDE + 4]);
            unsigned a3 = cvt_tf32(ka[(rbase + gr + 8) * KSTRIDE + 4]);
            const unsigned* bb = &smu[SM_B1 + gr * KSTRIDE + ks * 8 + tg];
            #pragma unroll
            for (int nf = 0; nf < 10; nf++) {
                unsigned b0 = bb[nf * 8 * KSTRIDE];
                unsigned b1v = bb[nf * 8 * KSTRIDE + 4];
                mma_tf32(d1[nf], a0, a1, a2, a3, b0, b1v);
            }
        }

        // h1 = sigmoid(D1 + qW) -> smem (tf32 bits), stride H1STRIDE
        #pragma unroll
        for (int nf = 0; nf < 10; nf++) {
            int j0 = nf * 8 + 2 * tg;
            float qlo = smf[SM_QW + j0], qhi = smf[SM_QW + j0 + 1];
            unsigned s0 = cvt_tf32(sigmoidf_fast(d1[nf][0] + qlo));
            unsigned s1 = cvt_tf32(sigmoidf_fast(d1[nf][1] + qhi));
            unsigned s2 = cvt_tf32(sigmoidf_fast(d1[nf][2] + qlo));
            unsigned s3 = cvt_tf32(sigmoidf_fast(d1[nf][3] + qhi));
            *(uint2*)&h1[gr * H1STRIDE + j0]       = make_uint2(s0, s1);
            *(uint2*)&h1[(gr + 8) * H1STRIDE + j0] = make_uint2(s2, s3);
        }
        __syncwarp();

        // MMA2: D2[16,40] = h1 @ W2T
        float d2[5][4];
        #pragma unroll
        for (int nf = 0; nf < 5; nf++)
            d2[nf][0] = d2[nf][1] = d2[nf][2] = d2[nf][3] = 0.0f;

        #pragma unroll
        for (int ks = 0; ks < 10; ks++) {
            const unsigned* ha = &h1[ks * 8 + tg];
            unsigned a0 = ha[gr * H1STRIDE];
            unsigned a1 = ha[(gr + 8) * H1STRIDE];
            unsigned a2 = ha[gr * H1STRIDE + 4];
            unsigned a3 = ha[(gr + 8) * H1STRIDE + 4];
            const unsigned* bb = &smu[SM_W2T + gr * W2TSTRIDE + ks * 8 + tg];
            #pragma unroll
            for (int nf = 0; nf < 5; nf++) {
                unsigned b0 = bb[nf * 8 * W2TSTRIDE];
                unsigned b1v = bb[nf * 8 * W2TSTRIDE + 4];
                mma_tf32(d2[nf], a0, a1, a2, a3, b0, b1v);
            }
        }

        // score = bd + sum_j sigmoid(D2+b2)*Wd ; reduce over tg
        float slo = 0.0f, shi = 0.0f;
        #pragma unroll
        for (int nf = 0; nf < 5; nf++) {
            int j0 = nf * 8 + 2 * tg;
            float blo = smf[SM_B2V + j0], bhi = smf[SM_B2V + j0 + 1];
            float wlo = smf[SM_WD + j0],  whi = smf[SM_WD + j0 + 1];
            slo += sigmoidf_fast(d2[nf][0] + blo) * wlo
                 + sigmoidf_fast(d2[nf][1] + bhi) * whi;
            shi += sigmoidf_fast(d2[nf][2] + blo) * wlo
                 + sigmoidf_fast(d2[nf][3] + bhi) * whi;
        }
        slo += __shfl_xor_sync(0xffffffffu, slo, 1);
        slo += __shfl_xor_sync(0xffffffffu, slo, 2);
        shi += __shfl_xor_sync(0xffffffffu, shi, 1);
        shi += __shfl_xor_sync(0xffffffffu, shi, 2);
        if (tg == 0) {
            int t0 = rbase + gr, t1 = rbase + gr + 8;
            if (t0 < L) smf[SM_SSC + t0] = slo + bdv;
            if (t1 < L) smf[SM_SSC + t1] = shi + bdv;
        }
    }
    __syncthreads();

    // ---- pooling: out[e] = sum_{t<L} score_t * k[t][e] ----
    {
        int e = tid & 63, half = tid >> 6;
        float acc = 0.0f;
        #pragma unroll 4
        for (int t = half; t < L; t += 2)
            acc += smf[SM_SSC + t] * smf[SM_K + t * KSTRIDE + e];
        smf[SM_PART + tid] = acc;
    }
    __syncthreads();
    if (tid < EE)
        out[b * EE + tid] = smf[SM_PART + tid] + smf[SM_PART + EE + tid];
}

extern "C" void kernel_launch(void* const* d_in, const int* in_sizes, int n_in,
                              void* d_out, int out_size)
{
    const float* query = (const float*)d_in[0];
    const float* keys  = (const float*)d_in[1];
    const void*  klen  = d_in[2];
    const float* W1    = (const float*)d_in[3];
    const float* b1    = (const float*)d_in[4];
    const float* W2    = (const float*)d_in[5];
    const float* b2    = (const float*)d_in[6];
    const float* Wd    = (const float*)d_in[7];
    const float* bd    = (const float*)d_in[8];
    float* out = (float*)d_out;

    const int B = in_sizes[0] / EE;  // 4096

    static int configured = 0;
    if (!configured) {
        cudaFuncSetAttribute(din_mma_kernel,
                             cudaFuncAttributeMaxDynamicSharedMemorySize, SM_BYTES);
        configured = 1;
    }

    prep_pack<<<20, 256>>>(W1, W2);
    prep_qw<<<B, 128>>>(query, b1);
    din_mma_kernel<<<B, 128, SM_BYTES>>>(query, keys, klen, b2, Wd, bd, out);
}